// round 11
// baseline (speedup 1.0000x reference)
#include <cuda_runtime.h>
#include <cuda_fp16.h>
#include <cstdint>
#include <math.h>

#define BB 32
#define SS 64
#define CC 256
#define N2 4096

#define ROWB 528                     // stage row stride (bytes): 512 data + 16 pad
#define STAGE_BYTES (32 * ROWB)      // 16896
#define DSM_BYTES (4 * STAGE_BYTES)  // 67584

__device__ int      g_videoOf[SS];
__device__ int      g_topk[SS];
__device__ float    g_negsum[SS];
__device__ float    g_all[SS * SS];
__device__ uint4    g_Afr[16 * 4 * 32];   // A fragments [ks][mt][lane] (fp16 pairs)
__device__ unsigned g_done;

__device__ __forceinline__ uint32_t smem_u32(const void* p) {
    uint32_t a;
    asm("{ .reg .u64 t; cvta.to.shared.u64 t, %1; cvt.u32.u64 %0, t; }" : "=r"(a) : "l"(p));
    return a;
}
#define CP16(dst, src) \
    asm volatile("cp.async.cg.shared.global [%0], [%1], 16;" :: "r"(dst), "l"(src))
#define CP_COMMIT() asm volatile("cp.async.commit_group;")
#define CP_WAIT2()  asm volatile("cp.async.wait_group 2;")

#define MMAF16(d, a0, a1, a2, a3, b0, b1) \
    asm volatile("mma.sync.aligned.m16n8k16.row.col.f32.f16.f16.f32 " \
                 "{%0,%1,%2,%3}, {%4,%5,%6,%7}, {%8,%9}, {%0,%1,%2,%3};" \
                 : "+f"((d)[0]), "+f"((d)[1]), "+f"((d)[2]), "+f"((d)[3]) \
                 : "r"(a0), "r"(a1), "r"(a2), "r"(a3), "r"(b0), "r"(b1))

// ---------------------------------------------------------------------------
// k_prep: bid<64 = sentence s: normalize -> fragment-order A; iou argmax.
//         bid==64: videoOf / negsum / g_done init.
__global__ void k_prep(const float* __restrict__ sents, const float* __restrict__ iou,
                       const int* __restrict__ ntgt) {
    int bid = blockIdx.x, tid = threadIdx.x;
    if (bid == 64) {
        if (tid < SS) g_negsum[tid] = 0.f;
        if (tid == 0) {
            g_done = 0u;
            int s = 0;
            for (int b = 0; b < BB; b++) {
                int n = ntgt[b];
                for (int k = 0; k < n && s < SS; k++) g_videoOf[s++] = b;
            }
            for (; s < SS; s++) g_videoOf[s] = BB - 1;
        }
        return;
    }
    int s = bid;
    int lane = tid & 31, w = tid >> 5;
    __shared__ float wsum[8];
    __shared__ float amax[8];
    __shared__ int   aidx[8];

    float x = sents[s * CC + tid];
    float q = x * x;
#pragma unroll
    for (int o = 16; o; o >>= 1) q += __shfl_xor_sync(~0u, q, o);
    if (lane == 0) wsum[w] = q;
    __syncthreads();
    float tot = wsum[0] + wsum[1] + wsum[2] + wsum[3] +
                wsum[4] + wsum[5] + wsum[6] + wsum[7];
    float inv = 1.f / fmaxf(sqrtf(tot), 1e-12f);
    __half h = __float2half_rn(x * inv);
    int c = tid;
    int u4 = ((c >> 4) * 4 + (s >> 4)) * 32 + (s & 7) * 4 + ((c & 7) >> 1);
    int byte = u4 * 16 + ((s >> 3) & 1) * 4 + ((c >> 3) & 1) * 8 + (c & 1) * 2;
    *(__half*)((char*)g_Afr + byte) = h;

    float best = -1.f;
    int bi = 0;
    const float* irow = iou + (size_t)s * N2;
#pragma unroll
    for (int k = 0; k < 16; k++) {
        int ij = tid + 256 * k;
        if ((ij & 63) >= (ij >> 6)) {
            float v = irow[ij];
            if (v > best) { best = v; bi = ij; }
        }
    }
#pragma unroll
    for (int o = 16; o; o >>= 1) {
        float ov = __shfl_xor_sync(~0u, best, o);
        int   oi = __shfl_xor_sync(~0u, bi, o);
        if (ov > best || (ov == best && oi < bi)) { best = ov; bi = oi; }
    }
    if (lane == 0) { amax[w] = best; aidx[w] = bi; }
    __syncthreads();
    if (tid == 0) {
        float bb = amax[0]; int ii = aidx[0];
        for (int k = 1; k < 8; k++)
            if (amax[k] > bb || (amax[k] == bb && aidx[k] < ii)) { bb = amax[k]; ii = aidx[k]; }
        g_topk[s] = ii;
    }
}

// ---------------------------------------------------------------------------
// k_main: CTA (t,b); cp.async ring of 32ch x 128prop fp32 stages; MMA straight
// from staged fp32 via conflict-free LDS; one barrier per stage.
__global__ void __launch_bounds__(256, 3) k_main(const float* __restrict__ video,
                                                 const float* __restrict__ iou,
                                                 float* __restrict__ out) {
    extern __shared__ __align__(16) char dsm[];
    __shared__ float sinv[128];
    __shared__ float sneg[SS];
    __shared__ float red[128];
    __shared__ int   caps[SS], capp[SS];
    __shared__ int   capc, flag;

    int tid = threadIdx.x;
    int lane = tid & 31, w = tid >> 5;
    int t = blockIdx.x, b = blockIdx.y;
    int ij0 = t * 128, i0 = 2 * t;
    int f0 = i0 >> 3, f1 = (i0 + 1) >> 3;
    int pstart0 = f0 * 8, pstart1 = 64 + f1 * 8;
    int seg0u = 16 - 2 * f0;
    int upr = 32 - 2 * (f0 + f1);

    // loader mapping: 8 threads per channel (32 ch per stage)
    int lch = tid >> 3, lj = tid & 7;
    const float* gch = video + (size_t)b * CC * N2 + ij0 + (size_t)lch * N2;
    uint32_t srow = smem_u32(dsm) + lch * ROWB;

    // prologue: stages 0,1
#pragma unroll
    for (int st = 0; st < 2; st++) {
        const float* gs = gch + (size_t)(st * 32) * N2;
#pragma unroll
        for (int u4 = 0; u4 < 4; u4++) {
            int u = lj + u4 * 8;
            if (u < upr) {
                int prop = (u < seg0u) ? (pstart0 + 4 * u) : (pstart1 + 4 * (u - seg0u));
                CP16(srow + st * STAGE_BYTES + prop * 4, gs + prop);
            }
        }
        CP_COMMIT();
    }

    if (tid == 0) capc = 0;
    if (tid < 64) sneg[tid] = 0.f;
    __syncthreads();
    if (tid >= 64 && tid < 128) {
        int s = tid - 64;
        if (g_videoOf[s] == b) {
            int tk = g_topk[s];
            if (tk >= ij0 && tk < ij0 + 128) {
                int c = atomicAdd(&capc, 1);
                caps[c] = s;
                capp[c] = tk - ij0;
            }
        }
    }

    int mt = w >> 1;          // m-tile: sents mt*16..mt*16+15
    int nh = w & 1;           // prop half: nh*64..nh*64+63
    int fmin = nh ? f1 : f0;  // first valid 8-prop block in this half (rows i0 / i0+1)
    int q = lane & 3, nl = lane >> 2;

    float acc[32];
#pragma unroll
    for (int k = 0; k < 32; k++) acc[k] = 0.f;
    float ssqp[8];
#pragma unroll
    for (int k = 0; k < 8; k++) ssqp[k] = 0.f;

    const uint4* Afr = g_Afr + lane;
    int cboff = q * (2 * ROWB) + (nh * 64 + nl) * 4;

    for (int st = 0; st < 8; st++) {
        // issue stage st+2
        if (st + 2 < 8) {
            const float* gs = gch + (size_t)((st + 2) * 32) * N2;
            uint32_t sd = srow + ((st + 2) & 3) * STAGE_BYTES;
#pragma unroll
            for (int u4 = 0; u4 < 4; u4++) {
                int u = lj + u4 * 8;
                if (u < upr) {
                    int prop = (u < seg0u) ? (pstart0 + 4 * u) : (pstart1 + 4 * (u - seg0u));
                    CP16(sd + prop * 4, gs + prop);
                }
            }
        }
        CP_COMMIT();
        CP_WAIT2();
        __syncthreads();

        const char* slot = dsm + (st & 3) * STAGE_BYTES;
#pragma unroll
        for (int kk = 0; kk < 2; kk++) {
            uint4 a = Afr[((st * 2 + kk) * 4 + mt) * 32];
            const char* cb = slot + kk * 16 * ROWB + cboff;
#pragma unroll
            for (int nt = 0; nt < 8; nt++) {
                if (nt < fmin) continue;
                const char* pbse = cb + nt * 32;
                float x0 = *(const float*)(pbse);
                float x1 = *(const float*)(pbse + ROWB);
                float x2 = *(const float*)(pbse + 8 * ROWB);
                float x3 = *(const float*)(pbse + 9 * ROWB);
                __half2 h0 = __floats2half2_rn(x0, x1);
                __half2 h1 = __floats2half2_rn(x2, x3);
                uint32_t b0u = *(uint32_t*)&h0, b1u = *(uint32_t*)&h1;
                MMAF16(acc + nt * 4, a.x, a.y, a.z, a.w, b0u, b1u);
                if (mt == 0)
                    ssqp[nt] += x0 * x0 + x1 * x1 + x2 * x2 + x3 * x3;
            }
        }
    }

    // per-prop inverse norms (mt==0 warps cover all 128 props)
    if (mt == 0) {
#pragma unroll
        for (int k = 0; k < 8; k++) {
            ssqp[k] += __shfl_xor_sync(~0u, ssqp[k], 1);
            ssqp[k] += __shfl_xor_sync(~0u, ssqp[k], 2);
        }
        if (q == 0) {
#pragma unroll
            for (int nt = 0; nt < 8; nt++)
                sinv[nh * 64 + nt * 8 + nl] = rsqrtf(fmaxf(ssqp[nt], 1e-24f));
        }
    }
    __syncthreads();

    // epilogue: mask + exp-sum + topk capture from accumulators
    int mrow = mt * 16;
    int pb = nh * 64;
    int ncap = capc;
    int s0 = mrow + nl, s1 = s0 + 8;
    bool home0 = (g_videoOf[s0] == b), home1 = (g_videoOf[s1] == b);
    const float* iou0 = iou + (size_t)s0 * N2 + ij0;
    const float* iou1 = iou + (size_t)s1 * N2 + ij0;
    float ls0 = 0.f, ls1 = 0.f;
#pragma unroll
    for (int f = 0; f < 8; f++) {
        if (f < fmin) continue;
#pragma unroll
        for (int e = 0; e < 2; e++) {
            int pl = pb + f * 8 + 2 * q + e;
            int ij = ij0 + pl;
            if ((ij & 63) < (ij >> 6)) continue;
            float inv = sinv[pl];
            float sc0 = acc[f * 4 + e] * inv;
            float sc1 = acc[f * 4 + 2 + e] * inv;
            if (!(home0 && iou0[pl] > 0.5f)) ls0 += __expf(sc0 * 10.f);
            if (!(home1 && iou1[pl] > 0.5f)) ls1 += __expf(sc1 * 10.f);
            for (int cc = 0; cc < ncap; cc++)
                if (capp[cc] == pl) {
                    g_all[caps[cc] * SS + s0] = sc0;
                    g_all[caps[cc] * SS + s1] = sc1;
                }
        }
    }
    ls0 += __shfl_xor_sync(~0u, ls0, 1); ls0 += __shfl_xor_sync(~0u, ls0, 2);
    ls1 += __shfl_xor_sync(~0u, ls1, 1); ls1 += __shfl_xor_sync(~0u, ls1, 2);
    if (q == 0) {
        atomicAdd(&sneg[s0], ls0);
        atomicAdd(&sneg[s1], ls1);
    }
    __syncthreads();
    if (tid < SS) atomicAdd(&g_negsum[tid], sneg[tid]);

    // last-CTA final reduction
    __threadfence();
    __syncthreads();
    if (tid == 0) flag = (atomicAdd(&g_done, 1u) == (unsigned)(32 * BB - 1));
    __syncthreads();
    if (flag) {
        if (tid < SS) {
            int s = tid;
            float pos = __ldcg(&g_all[s * SS + s]);
            float sum = 0.f;
            for (int u = 0; u < SS; u++)
                if (u != s) sum += expf(__ldcg(&g_all[s * SS + u]) * 10.f);
            float pv = pos * 10.f;
            red[s] = -(pv - logf(expf(pv) + sum));
            red[64 + s] = -(pv - logf(expf(pv) + __ldcg(&g_negsum[s])));
        }
        __syncthreads();
        if (tid == 0) {
            float a = 0.f, bq = 0.f;
            for (int u = 0; u < SS; u++) { a += red[u]; bq += red[64 + u]; }
            out[0] = a / SS;
            out[1] = bq / SS;
        }
    }
}

// ---------------------------------------------------------------------------
extern "C" void kernel_launch(void* const* d_in, const int* in_sizes, int n_in,
                              void* d_out, int out_size) {
    const float* video = (const float*)d_in[0];
    const float* sents = (const float*)d_in[1];
    const int*   ntgt  = (const int*)d_in[2];
    const float* iou   = (const float*)d_in[3];
    float* out = (float*)d_out;

    cudaFuncSetAttribute(k_main, cudaFuncAttributeMaxDynamicSharedMemorySize, DSM_BYTES);
    cudaFuncSetAttribute(k_main, cudaFuncAttributePreferredSharedMemoryCarveout, 100);

    k_prep<<<65, 256>>>(sents, iou, ntgt);
    k_main<<<dim3(32, BB), 256, DSM_BYTES>>>(video, iou, out);
}

// round 12
// speedup vs baseline: 1.4893x; 1.4893x over previous
#include <cuda_runtime.h>
#include <cuda_fp16.h>
#include <cstdint>
#include <math.h>

#define BB 32
#define SS 64
#define CC 256
#define N2 4096

#define ROWB 528                      // fp32 stage row stride (bytes) per channel
#define STAGE_BYTES (32 * ROWB)       // 16896
#define N_STAGE 3
#define BIMG_OFF (N_STAGE * STAGE_BYTES)   // 50688
#define BROW 80                       // fp16 B-image row stride per prop (64 data + 16 pad)
#define BIMG_BUF (128 * BROW)         // 10240
#define DSM_BYTES (BIMG_OFF + 2 * BIMG_BUF) // 71168

__device__ int      g_videoOf[SS];
__device__ int      g_topk[SS];
__device__ float    g_negsum[SS];
__device__ float    g_all[SS * SS];
__device__ uint4    g_Afr[16 * 4 * 32];   // A fragments [ks][mt][lane]
__device__ unsigned g_done;

__device__ __forceinline__ uint32_t smem_u32(const void* p) {
    uint32_t a;
    asm("{ .reg .u64 t; cvta.to.shared.u64 t, %1; cvt.u32.u64 %0, t; }" : "=r"(a) : "l"(p));
    return a;
}
#define CP16(dst, src) \
    asm volatile("cp.async.cg.shared.global [%0], [%1], 16;" :: "r"(dst), "l"(src))
#define CP_COMMIT() asm volatile("cp.async.commit_group;")
#define CP_WAIT2()  asm volatile("cp.async.wait_group 2;")

#define LDSM4(r0, r1, r2, r3, addr) \
    asm volatile("ldmatrix.sync.aligned.m8n8.x4.shared.b16 {%0,%1,%2,%3}, [%4];" \
                 : "=r"(r0), "=r"(r1), "=r"(r2), "=r"(r3) : "r"(addr))
#define MMAF16(d, a0, a1, a2, a3, b0, b1) \
    asm volatile("mma.sync.aligned.m16n8k16.row.col.f32.f16.f16.f32 " \
                 "{%0,%1,%2,%3}, {%4,%5,%6,%7}, {%8,%9}, {%0,%1,%2,%3};" \
                 : "+f"((d)[0]), "+f"((d)[1]), "+f"((d)[2]), "+f"((d)[3]) \
                 : "r"(a0), "r"(a1), "r"(a2), "r"(a3), "r"(b0), "r"(b1))

// ---------------------------------------------------------------------------
// k_prep: bid<64 = sentence s: normalize -> fragment-order A; iou argmax.
//         bid==64: videoOf / negsum / g_done init.
__global__ void k_prep(const float* __restrict__ sents, const float* __restrict__ iou,
                       const int* __restrict__ ntgt) {
    int bid = blockIdx.x, tid = threadIdx.x;
    if (bid == 64) {
        if (tid < SS) g_negsum[tid] = 0.f;
        if (tid == 0) {
            g_done = 0u;
            int s = 0;
            for (int b = 0; b < BB; b++) {
                int n = ntgt[b];
                for (int k = 0; k < n && s < SS; k++) g_videoOf[s++] = b;
            }
            for (; s < SS; s++) g_videoOf[s] = BB - 1;
        }
        return;
    }
    int s = bid;
    int lane = tid & 31, w = tid >> 5;
    __shared__ float wsum[8];
    __shared__ float amax[8];
    __shared__ int   aidx[8];

    float x = sents[s * CC + tid];
    float q = x * x;
#pragma unroll
    for (int o = 16; o; o >>= 1) q += __shfl_xor_sync(~0u, q, o);
    if (lane == 0) wsum[w] = q;
    __syncthreads();
    float tot = wsum[0] + wsum[1] + wsum[2] + wsum[3] +
                wsum[4] + wsum[5] + wsum[6] + wsum[7];
    float inv = 1.f / fmaxf(sqrtf(tot), 1e-12f);
    __half h = __float2half_rn(x * inv);
    int c = tid;
    int u4 = ((c >> 4) * 4 + (s >> 4)) * 32 + (s & 7) * 4 + ((c & 7) >> 1);
    int byte = u4 * 16 + ((s >> 3) & 1) * 4 + ((c >> 3) & 1) * 8 + (c & 1) * 2;
    *(__half*)((char*)g_Afr + byte) = h;

    float best = -1.f;
    int bi = 0;
    const float* irow = iou + (size_t)s * N2;
#pragma unroll
    for (int k = 0; k < 16; k++) {
        int ij = tid + 256 * k;
        if ((ij & 63) >= (ij >> 6)) {
            float v = irow[ij];
            if (v > best) { best = v; bi = ij; }
        }
    }
#pragma unroll
    for (int o = 16; o; o >>= 1) {
        float ov = __shfl_xor_sync(~0u, best, o);
        int   oi = __shfl_xor_sync(~0u, bi, o);
        if (ov > best || (ov == best && oi < bi)) { best = ov; bi = oi; }
    }
    if (lane == 0) { amax[w] = best; aidx[w] = bi; }
    __syncthreads();
    if (tid == 0) {
        float bb = amax[0]; int ii = aidx[0];
        for (int k = 1; k < 8; k++)
            if (amax[k] > bb || (amax[k] == bb && aidx[k] < ii)) { bb = amax[k]; ii = aidx[k]; }
        g_topk[s] = ii;
    }
}

// ---------------------------------------------------------------------------
// k_main: CTA (t,b). cp.async fp32 ring -> single-pass fp16 convert (double-
// buffered B-image) -> ldmatrix + HMMA. 2 barriers/stage.
__global__ void __launch_bounds__(256, 3) k_main(const float* __restrict__ video,
                                                 const float* __restrict__ iou,
                                                 float* __restrict__ out) {
    extern __shared__ __align__(16) char dsm[];
    __shared__ float ssq[256];
    __shared__ float sinv[128];
    __shared__ float sneg[SS];
    __shared__ float red[128];
    __shared__ int   caps[SS], capp[SS];
    __shared__ int   capc, flag;

    int tid = threadIdx.x;
    int lane = tid & 31, w = tid >> 5;
    int t = blockIdx.x, b = blockIdx.y;
    int ij0 = t * 128, i0 = 2 * t;
    int f0 = i0 >> 3, f1 = (i0 + 1) >> 3;
    int pstart0 = f0 * 8, pstart1 = 64 + f1 * 8;
    int seg0u = 16 - 2 * f0;
    int upr = 32 - 2 * (f0 + f1);

    // loader mapping: 8 threads per channel row (32 ch per stage)
    int lch = tid >> 3, lj = tid & 7;
    const float* gch = video + (size_t)b * CC * N2 + ij0 + (size_t)lch * N2;
    uint32_t srow = smem_u32(dsm) + lch * ROWB;

    // prologue: stages 0,1
#pragma unroll
    for (int st = 0; st < 2; st++) {
        const float* gs = gch + (size_t)(st * 32) * N2;
#pragma unroll
        for (int u4 = 0; u4 < 4; u4++) {
            int u = lj + u4 * 8;
            if (u < upr) {
                int prop = (u < seg0u) ? (pstart0 + 4 * u) : (pstart1 + 4 * (u - seg0u));
                CP16(srow + st * STAGE_BYTES + prop * 4, gs + prop);
            }
        }
        CP_COMMIT();
    }

    if (tid == 0) capc = 0;
    if (tid < 64) sneg[tid] = 0.f;
    __syncthreads();
    if (tid >= 64 && tid < 128) {
        int s = tid - 64;
        if (g_videoOf[s] == b) {
            int tk = g_topk[s];
            if (tk >= ij0 && tk < ij0 + 128) {
                int c = atomicAdd(&capc, 1);
                caps[c] = s;
                capp[c] = tk - ij0;
            }
        }
    }

    // convert mapping
    int cp_ = tid & 127, chalf = tid >> 7;
    bool cact = (cp_ < 64) ? (cp_ >= pstart0) : (cp_ >= pstart1);
    const char* cvsrc = dsm + cp_ * 4 + chalf * (16 * ROWB);
    char* cvdst = dsm + BIMG_OFF + cp_ * BROW + chalf * 32;
    float myssq = 0.f;

    // MMA mapping: warp = (mt, nh)
    int mt = w >> 1, nh = w & 1;
    int fmin = nh ? f1 : f0;
    int pb = nh * 64;
    int g = lane >> 3, r = lane & 7;
    int brow_l = ((g & 1) << 3) + r;
    int kbyte = (g >> 1) << 4;
    uint32_t Bb = smem_u32(dsm) + BIMG_OFF + (pb + brow_l) * BROW + kbyte;
    const uint4* Afr = g_Afr + lane;

    float acc[32];
#pragma unroll
    for (int k = 0; k < 32; k++) acc[k] = 0.f;

    for (int st = 0; st < 8; st++) {
        // issue stage st+2 into ring slot (st+2)%3
        if (st + 2 < 8) {
            const float* gs = gch + (size_t)((st + 2) * 32) * N2;
            uint32_t sd = srow + ((st + 2) % N_STAGE) * STAGE_BYTES;
#pragma unroll
            for (int u4 = 0; u4 < 4; u4++) {
                int u = lj + u4 * 8;
                if (u < upr) {
                    int prop = (u < seg0u) ? (pstart0 + 4 * u) : (pstart1 + 4 * (u - seg0u));
                    CP16(sd + prop * 4, gs + prop);
                }
            }
        }
        CP_COMMIT();
        CP_WAIT2();
        __syncthreads();   // stage st ready; prior MMA reads of this B-buf done

        // convert: fp32 stage -> fp16 B-image (each prop-half converted ONCE)
        int bufo = (st & 1) * BIMG_BUF;
        if (cact) {
            const char* sp = cvsrc + (st % N_STAGE) * STAGE_BYTES;
            uint32_t wv[8];
#pragma unroll
            for (int k = 0; k < 16; k += 2) {
                float x0 = *(const float*)(sp + (size_t)k * ROWB);
                float x1 = *(const float*)(sp + (size_t)(k + 1) * ROWB);
                myssq += x0 * x0 + x1 * x1;
                __half2 hp = __floats2half2_rn(x0, x1);
                wv[k >> 1] = *(uint32_t*)&hp;
            }
            uint4* d = (uint4*)(cvdst + bufo);
            d[0] = make_uint4(wv[0], wv[1], wv[2], wv[3]);
            d[1] = make_uint4(wv[4], wv[5], wv[6], wv[7]);
        }
        __syncthreads();   // B-image ready

        // MMA: 2 k-steps of 16 ch
#pragma unroll
        for (int kk = 0; kk < 2; kk++) {
            uint4 a = Afr[((st * 2 + kk) * 4 + mt) * 32];
            uint32_t badr0 = Bb + bufo + kk * 32;
#pragma unroll
            for (int fp = 0; fp < 4; fp++) {
                int f = fp * 2;
                if (f + 1 < fmin) continue;
                uint32_t b0, b1, b2, b3;
                LDSM4(b0, b1, b2, b3, badr0 + f * 8 * BROW);
                if (f >= fmin) MMAF16(acc + f * 4, a.x, a.y, a.z, a.w, b0, b2);
                MMAF16(acc + f * 4 + 4, a.x, a.y, a.z, a.w, b1, b3);
            }
        }
    }

    // per-prop inverse norms
    ssq[tid] = myssq;
    __syncthreads();
    if (tid < 128)
        sinv[tid] = rsqrtf(fmaxf(ssq[tid] + ssq[tid + 128], 1e-24f));
    __syncthreads();

    // epilogue: mask + exp-sum + topk capture
    int q = lane & 3, nl = lane >> 2;
    int ncap = capc;
    int s0 = mt * 16 + nl, s1 = s0 + 8;
    bool home0 = (g_videoOf[s0] == b), home1 = (g_videoOf[s1] == b);
    const float* iou0 = iou + (size_t)s0 * N2 + ij0;
    const float* iou1 = iou + (size_t)s1 * N2 + ij0;
    float ls0 = 0.f, ls1 = 0.f;
#pragma unroll
    for (int f = 0; f < 8; f++) {
        if (f < fmin) continue;
#pragma unroll
        for (int e = 0; e < 2; e++) {
            int pl = pb + f * 8 + 2 * q + e;
            int ij = ij0 + pl;
            if ((ij & 63) < (ij >> 6)) continue;
            float inv = sinv[pl];
            float sc0 = acc[f * 4 + e] * inv;
            float sc1 = acc[f * 4 + 2 + e] * inv;
            if (!(home0 && iou0[pl] > 0.5f)) ls0 += __expf(sc0 * 10.f);
            if (!(home1 && iou1[pl] > 0.5f)) ls1 += __expf(sc1 * 10.f);
            for (int cc = 0; cc < ncap; cc++)
                if (capp[cc] == pl) {
                    g_all[caps[cc] * SS + s0] = sc0;
                    g_all[caps[cc] * SS + s1] = sc1;
                }
        }
    }
    ls0 += __shfl_xor_sync(~0u, ls0, 1); ls0 += __shfl_xor_sync(~0u, ls0, 2);
    ls1 += __shfl_xor_sync(~0u, ls1, 1); ls1 += __shfl_xor_sync(~0u, ls1, 2);
    if (q == 0) {
        atomicAdd(&sneg[s0], ls0);
        atomicAdd(&sneg[s1], ls1);
    }
    __syncthreads();
    if (tid < SS) atomicAdd(&g_negsum[tid], sneg[tid]);

    // last-CTA final reduction
    __threadfence();
    __syncthreads();
    if (tid == 0) flag = (atomicAdd(&g_done, 1u) == (unsigned)(32 * BB - 1));
    __syncthreads();
    if (flag) {
        if (tid < SS) {
            int s = tid;
            float pos = __ldcg(&g_all[s * SS + s]);
            float sum = 0.f;
            for (int u = 0; u < SS; u++)
                if (u != s) sum += expf(__ldcg(&g_all[s * SS + u]) * 10.f);
            float pv = pos * 10.f;
            red[s] = -(pv - logf(expf(pv) + sum));
            red[64 + s] = -(pv - logf(expf(pv) + __ldcg(&g_negsum[s])));
        }
        __syncthreads();
        if (tid == 0) {
            float a = 0.f, bq = 0.f;
            for (int u = 0; u < SS; u++) { a += red[u]; bq += red[64 + u]; }
            out[0] = a / SS;
            out[1] = bq / SS;
        }
    }
}

// ---------------------------------------------------------------------------
extern "C" void kernel_launch(void* const* d_in, const int* in_sizes, int n_in,
                              void* d_out, int out_size) {
    const float* video = (const float*)d_in[0];
    const float* sents = (const float*)d_in[1];
    const int*   ntgt  = (const int*)d_in[2];
    const float* iou   = (const float*)d_in[3];
    float* out = (float*)d_out;

    cudaFuncSetAttribute(k_main, cudaFuncAttributeMaxDynamicSharedMemorySize, DSM_BYTES);
    cudaFuncSetAttribute(k_main, cudaFuncAttributePreferredSharedMemoryCarveout, 100);

    k_prep<<<65, 256>>>(sents, iou, ntgt);
    k_main<<<dim3(32, BB), 256, DSM_BYTES>>>(video, iou, out);
}